// round 1
// baseline (speedup 1.0000x reference)
#include <cuda_runtime.h>
#include <cuda_bf16.h>
#include <math.h>
#include <stdint.h>

// ---------------- problem constants ----------------
#define BB   16384
#define DIM  1024
#define HH   16
#define HD   64
#define FFN  4096
#define LNEPS 1e-5f

#define BD   ((size_t)BB * DIM)          // 16,777,216
#define BF   ((size_t)BB * FFN)          // 67,108,864
#define WSZ  (1024*1024)                 // one DIMxDIM weight

// ---------------- scratch (static device globals; allocation-free rule) ----
__device__ float g_mean[BD];
__device__ float g_qin [BD];
__device__ float g_q   [BD];
__device__ float g_K   [3 * BD];
__device__ float g_V   [3 * BD];
__device__ float g_x   [BD];
__device__ float g_y   [BD];
__device__ float g_h   [BF];
__device__ float g_mods[3 * BD];          // tf32-rounded copies of m0..m2
__device__ float g_w   [4 * WSZ + 2 * (size_t)DIM * FFN];  // rounded weights

// ---------------- helpers ----------------
__device__ __forceinline__ float rnd_tf32(float x) {
    uint32_t u;
    asm("cvt.rna.tf32.f32 %0, %1;" : "=r"(u) : "f"(x));
    return __uint_as_float(u);
}
__device__ __forceinline__ uint32_t f2b(float f) { return __float_as_uint(f); }

// ---------------- elementwise prep kernels ----------------
__global__ void round_copy4_k(const float4* __restrict__ s, float4* __restrict__ d, int n4) {
    int i = blockIdx.x * blockDim.x + threadIdx.x;
    int st = gridDim.x * blockDim.x;
    for (; i < n4; i += st) {
        float4 v = s[i];
        v.x = rnd_tf32(v.x); v.y = rnd_tf32(v.y);
        v.z = rnd_tf32(v.z); v.w = rnd_tf32(v.w);
        d[i] = v;
    }
}

__global__ void mean4_k(const float4* __restrict__ a, const float4* __restrict__ b,
                        const float4* __restrict__ c, float4* __restrict__ o, int n4) {
    int i = blockIdx.x * blockDim.x + threadIdx.x;
    int st = gridDim.x * blockDim.x;
    const float third = 1.f / 3.f;
    for (; i < n4; i += st) {
        float4 x = a[i], y = b[i], z = c[i], r;
        r.x = rnd_tf32((x.x + y.x + z.x) * third);
        r.y = rnd_tf32((x.y + y.y + z.y) * third);
        r.z = rnd_tf32((x.z + y.z + z.z) * third);
        r.w = rnd_tf32((x.w + y.w + z.w) * third);
        o[i] = r;
    }
}

// ---------------- tf32 mma.sync GEMM ----------------
// C[M,N] = A[M,K] @ W[K,N] + bias, tiles 128x128x32, 256 threads, 8 warps (4m x 2n),
// warp tile 32x64 = 2 x 8 mma(16x8) tiles. cp.async double-buffered smem.
#define BM 128
#define BN 128
#define BK 32
#define ASTR 36     // padded A row stride (floats): (4g+tig) banks distinct
#define BSTR 136    // padded B row stride: (8k+g) banks distinct
#define A_ELEMS (BM * ASTR)   // 4608
#define B_ELEMS (BK * BSTR)   // 4352
#define GEMM_SMEM_BYTES ((2 * (A_ELEMS + B_ELEMS)) * 4)   // 71680

// MODE: 0 = plain (+bias), 1 = QIN (+bias +add, tf32-round), 2 = relu(+bias), tf32-round
template <int MODE>
__global__ __launch_bounds__(256, 1) void gemm_tf32_kernel(
    const float* __restrict__ A0, const float* __restrict__ A1, const float* __restrict__ A2,
    const float* __restrict__ W,  const float* __restrict__ bias,
    const float* __restrict__ addsrc,
    float* __restrict__ C0, float* __restrict__ C1, float* __restrict__ C2,
    int K, int N)
{
    extern __shared__ float smem[];
    float* As = smem;
    float* Bs = smem + 2 * A_ELEMS;

    const float* A = (blockIdx.z == 0) ? A0 : (blockIdx.z == 1) ? A1 : A2;
    float*       C = (blockIdx.z == 0) ? C0 : (blockIdx.z == 1) ? C1 : C2;

    const int m0 = blockIdx.y * BM, n0 = blockIdx.x * BN;
    const int tid  = threadIdx.x;
    const int lane = tid & 31, warp = tid >> 5;
    const int wm = warp & 3, wn = warp >> 2;
    const int g = lane >> 2, tig = lane & 3;

    const uint32_t sm_a = (uint32_t)__cvta_generic_to_shared(As);
    const uint32_t sm_b = (uint32_t)__cvta_generic_to_shared(Bs);

    // stage loader
    auto load_stage = [&](int stage, int kb) {
        const float* Ag = A + (size_t)m0 * K + kb;
        #pragma unroll
        for (int p = 0; p < 4; p++) {
            int m = (tid >> 3) + p * 32, kc = (tid & 7) * 4;
            uint32_t dst = sm_a + (uint32_t)(stage * A_ELEMS + m * ASTR + kc) * 4;
            const float* src = Ag + (size_t)m * K + kc;
            asm volatile("cp.async.cg.shared.global [%0], [%1], 16;\n" :: "r"(dst), "l"(src));
        }
        const float* Bg = W + (size_t)kb * N + n0;
        #pragma unroll
        for (int p = 0; p < 4; p++) {
            int k = (tid >> 5) + p * 8, nc = (tid & 31) * 4;
            uint32_t dst = sm_b + (uint32_t)(stage * B_ELEMS + k * BSTR + nc) * 4;
            const float* src = Bg + (size_t)k * N + nc;
            asm volatile("cp.async.cg.shared.global [%0], [%1], 16;\n" :: "r"(dst), "l"(src));
        }
    };

    float c[2][8][4];
    #pragma unroll
    for (int i = 0; i < 2; i++)
        #pragma unroll
        for (int j = 0; j < 8; j++)
            #pragma unroll
            for (int l = 0; l < 4; l++) c[i][j][l] = 0.f;

    load_stage(0, 0);
    asm volatile("cp.async.commit_group;\n");
    asm volatile("cp.async.wait_group 0;\n");
    __syncthreads();

    const int KT = K / BK;
    for (int kt = 0; kt < KT; ++kt) {
        int cur = kt & 1;
        if (kt + 1 < KT) {
            load_stage(cur ^ 1, (kt + 1) * BK);
            asm volatile("cp.async.commit_group;\n");
        }
        const float* as = As + cur * A_ELEMS;
        const float* bs = Bs + cur * B_ELEMS;
        #pragma unroll
        for (int kk = 0; kk < BK; kk += 8) {
            uint32_t a[2][4], b[8][2];
            #pragma unroll
            for (int mi = 0; mi < 2; mi++) {
                int r = wm * 32 + mi * 16 + g;
                const float* ap = as + r * ASTR + kk + tig;
                a[mi][0] = f2b(ap[0]);
                a[mi][1] = f2b(ap[8 * ASTR]);
                a[mi][2] = f2b(ap[4]);
                a[mi][3] = f2b(ap[8 * ASTR + 4]);
            }
            #pragma unroll
            for (int ni = 0; ni < 8; ni++) {
                int col = wn * 64 + ni * 8 + g;
                const float* bp = bs + (kk + tig) * BSTR + col;
                b[ni][0] = f2b(bp[0]);
                b[ni][1] = f2b(bp[4 * BSTR]);
            }
            #pragma unroll
            for (int mi = 0; mi < 2; mi++)
                #pragma unroll
                for (int ni = 0; ni < 8; ni++) {
                    float* cc = c[mi][ni];
                    asm volatile(
                        "mma.sync.aligned.m16n8k8.row.col.f32.tf32.tf32.f32 "
                        "{%0,%1,%2,%3},{%4,%5,%6,%7},{%8,%9},{%0,%1,%2,%3};\n"
                        : "+f"(cc[0]), "+f"(cc[1]), "+f"(cc[2]), "+f"(cc[3])
                        : "r"(a[mi][0]), "r"(a[mi][1]), "r"(a[mi][2]), "r"(a[mi][3]),
                          "r"(b[ni][0]), "r"(b[ni][1]));
                }
        }
        if (kt + 1 < KT) {
            asm volatile("cp.async.wait_group 0;\n");
            __syncthreads();
        }
    }

    // epilogue
    #pragma unroll
    for (int mi = 0; mi < 2; mi++) {
        int row = m0 + wm * 32 + mi * 16 + g;
        #pragma unroll
        for (int ni = 0; ni < 8; ni++) {
            int col = n0 + wn * 64 + ni * 8 + tig * 2;
            float bv0 = bias[col], bv1 = bias[col + 1];
            float v0 = c[mi][ni][0] + bv0, v1 = c[mi][ni][1] + bv1;
            float v2 = c[mi][ni][2] + bv0, v3 = c[mi][ni][3] + bv1;
            size_t i0 = (size_t)row * N + col;
            size_t i1 = (size_t)(row + 8) * N + col;
            if (MODE == 1) {
                v0 = rnd_tf32(v0 + addsrc[i0]);     v1 = rnd_tf32(v1 + addsrc[i0 + 1]);
                v2 = rnd_tf32(v2 + addsrc[i1]);     v3 = rnd_tf32(v3 + addsrc[i1 + 1]);
            } else if (MODE == 2) {
                v0 = rnd_tf32(fmaxf(v0, 0.f)); v1 = rnd_tf32(fmaxf(v1, 0.f));
                v2 = rnd_tf32(fmaxf(v2, 0.f)); v3 = rnd_tf32(fmaxf(v3, 0.f));
            }
            float2 p0 = make_float2(v0, v1);
            float2 p1 = make_float2(v2, v3);
            *(float2*)&C[i0] = p0;
            *(float2*)&C[i1] = p1;
        }
    }
}

// ---------------- attention (3 keys) + residual + LN1 ----------------
__global__ __launch_bounds__(512) void attn_ln1_k(
    const float* __restrict__ q,
    const float* __restrict__ K0, const float* __restrict__ K1, const float* __restrict__ K2,
    const float* __restrict__ V0, const float* __restrict__ V1, const float* __restrict__ V2,
    const float* __restrict__ dom, const float* __restrict__ gam, const float* __restrict__ bet,
    float* __restrict__ xo)
{
    __shared__ float sout[DIM];
    __shared__ float rS[16], rQ[16], stats[2];
    const int b = blockIdx.x, tid = threadIdx.x;
    const int h = tid >> 5, lane = tid & 31;
    const size_t rowb = (size_t)b * DIM;
    const size_t off = rowb + h * HD + lane * 2;

    float2 qv = *(const float2*)(q + off);
    float2 k0 = *(const float2*)(K0 + off);
    float2 k1 = *(const float2*)(K1 + off);
    float2 k2 = *(const float2*)(K2 + off);
    float d0 = qv.x * k0.x + qv.y * k0.y;
    float d1 = qv.x * k1.x + qv.y * k1.y;
    float d2 = qv.x * k2.x + qv.y * k2.y;
    #pragma unroll
    for (int o = 16; o; o >>= 1) {
        d0 += __shfl_xor_sync(0xffffffffu, d0, o);
        d1 += __shfl_xor_sync(0xffffffffu, d1, o);
        d2 += __shfl_xor_sync(0xffffffffu, d2, o);
    }
    float s0 = d0 * 0.125f, s1 = d1 * 0.125f, s2 = d2 * 0.125f;
    float mx = fmaxf(s0, fmaxf(s1, s2));
    float e0 = expf(s0 - mx), e1 = expf(s1 - mx), e2 = expf(s2 - mx);
    float inv = 1.f / (e0 + e1 + e2);
    float p0 = e0 * inv, p1 = e1 * inv, p2 = e2 * inv;

    float2 v0 = *(const float2*)(V0 + off);
    float2 v1 = *(const float2*)(V1 + off);
    float2 v2 = *(const float2*)(V2 + off);
    float ox = p0 * v0.x + p1 * v1.x + p2 * v2.x;
    float oy = p0 * v0.y + p1 * v1.y + p2 * v2.y;
    int dloc = h * HD + lane * 2;
    sout[dloc] = ox;
    sout[dloc + 1] = oy;
    __syncthreads();

    int d0i = tid * 2;
    float t0 = dom[rowb + d0i]     + sout[d0i];
    float t1 = dom[rowb + d0i + 1] + sout[d0i + 1];
    float s = t0 + t1, sq = t0 * t0 + t1 * t1;
    #pragma unroll
    for (int o = 16; o; o >>= 1) {
        s  += __shfl_xor_sync(0xffffffffu, s, o);
        sq += __shfl_xor_sync(0xffffffffu, sq, o);
    }
    if (lane == 0) { rS[h] = s; rQ[h] = sq; }
    __syncthreads();
    if (tid == 0) {
        float S = 0.f, Q = 0.f;
        #pragma unroll
        for (int i = 0; i < 16; i++) { S += rS[i]; Q += rQ[i]; }
        float mu = S * (1.f / DIM);
        float var = Q * (1.f / DIM) - mu * mu;
        stats[0] = mu;
        stats[1] = rsqrtf(var + LNEPS);
    }
    __syncthreads();
    float mu = stats[0], r = stats[1];
    xo[rowb + d0i]     = rnd_tf32((t0 - mu) * r * gam[d0i]     + bet[d0i]);
    xo[rowb + d0i + 1] = rnd_tf32((t1 - mu) * r * gam[d0i + 1] + bet[d0i + 1]);
}

// ---------------- residual + LN2 + [DIM,3] matvec + softmax ----------------
__global__ __launch_bounds__(256) void final_k(
    const float* __restrict__ x, const float* __restrict__ y,
    const float* __restrict__ g2, const float* __restrict__ b2,
    const float* __restrict__ Ww, const float* __restrict__ bw,
    float* __restrict__ out)
{
    __shared__ float rs[8], rq[8], rl[8][3], stats[2];
    const int b = blockIdx.x, tid = threadIdx.x;
    const int lane = tid & 31, w = tid >> 5;
    const size_t base = (size_t)b * DIM;

    float t[4];
    float s = 0.f, sq = 0.f;
    #pragma unroll
    for (int i = 0; i < 4; i++) {
        int d = tid + i * 256;
        float v = x[base + d] + y[base + d];
        t[i] = v; s += v; sq += v * v;
    }
    #pragma unroll
    for (int o = 16; o; o >>= 1) {
        s  += __shfl_xor_sync(0xffffffffu, s, o);
        sq += __shfl_xor_sync(0xffffffffu, sq, o);
    }
    if (lane == 0) { rs[w] = s; rq[w] = sq; }
    __syncthreads();
    if (tid == 0) {
        float S = 0.f, Q = 0.f;
        #pragma unroll
        for (int i = 0; i < 8; i++) { S += rs[i]; Q += rq[i]; }
        float mu = S * (1.f / DIM);
        float var = Q * (1.f / DIM) - mu * mu;
        stats[0] = mu;
        stats[1] = rsqrtf(var + LNEPS);
    }
    __syncthreads();
    float mu = stats[0], r = stats[1];
    float l0 = 0.f, l1 = 0.f, l2 = 0.f;
    #pragma unroll
    for (int i = 0; i < 4; i++) {
        int d = tid + i * 256;
        float xn = (t[i] - mu) * r * g2[d] + b2[d];
        l0 += xn * Ww[d * 3];
        l1 += xn * Ww[d * 3 + 1];
        l2 += xn * Ww[d * 3 + 2];
    }
    #pragma unroll
    for (int o = 16; o; o >>= 1) {
        l0 += __shfl_xor_sync(0xffffffffu, l0, o);
        l1 += __shfl_xor_sync(0xffffffffu, l1, o);
        l2 += __shfl_xor_sync(0xffffffffu, l2, o);
    }
    if (lane == 0) { rl[w][0] = l0; rl[w][1] = l1; rl[w][2] = l2; }
    __syncthreads();
    if (tid == 0) {
        float a0 = bw[0], a1 = bw[1], a2 = bw[2];
        #pragma unroll
        for (int i = 0; i < 8; i++) { a0 += rl[i][0]; a1 += rl[i][1]; a2 += rl[i][2]; }
        float m = fmaxf(a0, fmaxf(a1, a2));
        float e0 = expf(a0 - m), e1 = expf(a1 - m), e2 = expf(a2 - m);
        float inv = 1.f / (e0 + e1 + e2);
        out[(size_t)b * 3]     = e0 * inv;
        out[(size_t)b * 3 + 1] = e1 * inv;
        out[(size_t)b * 3 + 2] = e2 * inv;
    }
}

// ---------------- host launcher ----------------
extern "C" void kernel_launch(void* const* d_in, const int* in_sizes, int n_in,
                              void* d_out, int out_size)
{
    (void)in_sizes; (void)n_in; (void)out_size;
    const float* m0  = (const float*)d_in[0];
    const float* m1  = (const float*)d_in[1];
    const float* m2  = (const float*)d_in[2];
    const float* dom = (const float*)d_in[3];
    const float* Wg  = (const float*)d_in[4];
    const float* bg  = (const float*)d_in[5];
    const float* Wq  = (const float*)d_in[6];
    const float* bq  = (const float*)d_in[7];
    const float* Wk  = (const float*)d_in[8];
    const float* bk  = (const float*)d_in[9];
    const float* Wv  = (const float*)d_in[10];
    const float* bv  = (const float*)d_in[11];
    const float* W1  = (const float*)d_in[12];
    const float* b1  = (const float*)d_in[13];
    const float* W2  = (const float*)d_in[14];
    const float* b2  = (const float*)d_in[15];
    const float* g1  = (const float*)d_in[16];
    const float* be1 = (const float*)d_in[17];
    const float* g2  = (const float*)d_in[18];
    const float* be2 = (const float*)d_in[19];
    const float* Ww  = (const float*)d_in[20];
    const float* bw  = (const float*)d_in[21];
    float* out = (float*)d_out;

    float *pmean, *pqin, *pq, *pK, *pV, *px, *py, *ph, *pmods, *pw;
    cudaGetSymbolAddress((void**)&pmean, g_mean);
    cudaGetSymbolAddress((void**)&pqin,  g_qin);
    cudaGetSymbolAddress((void**)&pq,    g_q);
    cudaGetSymbolAddress((void**)&pK,    g_K);
    cudaGetSymbolAddress((void**)&pV,    g_V);
    cudaGetSymbolAddress((void**)&px,    g_x);
    cudaGetSymbolAddress((void**)&py,    g_y);
    cudaGetSymbolAddress((void**)&ph,    g_h);
    cudaGetSymbolAddress((void**)&pmods, g_mods);
    cudaGetSymbolAddress((void**)&pw,    g_w);

    float* Wg_r = pw;
    float* Wq_r = pw + (size_t)WSZ;
    float* Wk_r = pw + (size_t)2 * WSZ;
    float* Wv_r = pw + (size_t)3 * WSZ;
    float* W1_r = pw + (size_t)4 * WSZ;
    float* W2_r = W1_r + (size_t)DIM * FFN;

    cudaFuncSetAttribute(gemm_tf32_kernel<0>, cudaFuncAttributeMaxDynamicSharedMemorySize, GEMM_SMEM_BYTES);
    cudaFuncSetAttribute(gemm_tf32_kernel<1>, cudaFuncAttributeMaxDynamicSharedMemorySize, GEMM_SMEM_BYTES);
    cudaFuncSetAttribute(gemm_tf32_kernel<2>, cudaFuncAttributeMaxDynamicSharedMemorySize, GEMM_SMEM_BYTES);

    const int RT = 256;
    // tf32-round weights + modality activations
    round_copy4_k<<<2048, RT>>>((const float4*)Wg, (float4*)Wg_r, WSZ / 4);
    round_copy4_k<<<2048, RT>>>((const float4*)Wq, (float4*)Wq_r, WSZ / 4);
    round_copy4_k<<<2048, RT>>>((const float4*)Wk, (float4*)Wk_r, WSZ / 4);
    round_copy4_k<<<2048, RT>>>((const float4*)Wv, (float4*)Wv_r, WSZ / 4);
    round_copy4_k<<<4096, RT>>>((const float4*)W1, (float4*)W1_r, (int)((size_t)DIM * FFN / 4));
    round_copy4_k<<<4096, RT>>>((const float4*)W2, (float4*)W2_r, (int)((size_t)DIM * FFN / 4));
    round_copy4_k<<<8192, RT>>>((const float4*)m0, (float4*)(pmods),          (int)(BD / 4));
    round_copy4_k<<<8192, RT>>>((const float4*)m1, (float4*)(pmods + BD),     (int)(BD / 4));
    round_copy4_k<<<8192, RT>>>((const float4*)m2, (float4*)(pmods + 2 * BD), (int)(BD / 4));
    // mean of modalities (tf32-rounded, GEMM input)
    mean4_k<<<8192, RT>>>((const float4*)m0, (const float4*)m1, (const float4*)m2,
                          (float4*)pmean, (int)(BD / 4));

    dim3 gD(DIM / BN, BB / BM, 1);   // N=1024 GEMMs
    dim3 gF(FFN / BN, BB / BM, 1);   // N=4096 GEMM
    dim3 gKV(DIM / BN, BB / BM, 3);  // batched over 3 modalities

    // qin = tf32( domain + mean@Wg + bg )
    gemm_tf32_kernel<1><<<gD, 256, GEMM_SMEM_BYTES>>>(
        pmean, pmean, pmean, Wg_r, bg, dom, pqin, pqin, pqin, DIM, DIM);
    // q = qin@Wq + bq
    gemm_tf32_kernel<0><<<gD, 256, GEMM_SMEM_BYTES>>>(
        pqin, pqin, pqin, Wq_r, bq, nullptr, pq, pq, pq, DIM, DIM);
    // K_j = m_j@Wk + bk   (z-batched)
    gemm_tf32_kernel<0><<<gKV, 256, GEMM_SMEM_BYTES>>>(
        pmods, pmods + BD, pmods + 2 * BD, Wk_r, bk, nullptr,
        pK, pK + BD, pK + 2 * BD, DIM, DIM);
    // V_j = m_j@Wv + bv
    gemm_tf32_kernel<0><<<gKV, 256, GEMM_SMEM_BYTES>>>(
        pmods, pmods + BD, pmods + 2 * BD, Wv_r, bv, nullptr,
        pV, pV + BD, pV + 2 * BD, DIM, DIM);

    // attention over 3 keys + residual + LN1 -> x (tf32-rounded)
    attn_ln1_k<<<BB, 512>>>(pq, pK, pK + BD, pK + 2 * BD,
                            pV, pV + BD, pV + 2 * BD,
                            dom, g1, be1, px);

    // h = tf32(relu(x@W1 + b1))
    gemm_tf32_kernel<2><<<gF, 256, GEMM_SMEM_BYTES>>>(
        px, px, px, W1_r, b1, nullptr, ph, ph, ph, DIM, FFN);
    // y = h@W2 + b2
    gemm_tf32_kernel<0><<<gD, 256, GEMM_SMEM_BYTES>>>(
        ph, ph, ph, W2_r, b2, nullptr, py, py, py, FFN, DIM);

    // LN2 + Ww matvec + softmax
    final_k<<<BB, 256>>>(px, py, g2, be2, Ww, bw, out);
}

// round 6
// speedup vs baseline: 1.7961x; 1.7961x over previous
#include <cuda_runtime.h>
#include <cuda_fp16.h>
#include <math.h>
#include <stdint.h>

// ---------------- problem constants ----------------
#define BB   16384
#define DIM  1024
#define HH   16
#define HD   64
#define FFN  4096
#define LNEPS 1e-5f

#define BD   ((size_t)BB * DIM)
#define BF   ((size_t)BB * FFN)
#define WSZ  (1024*1024)

// ---------------- scratch ----------------
__device__ __half g_mods[3 * BD];     // fp16 modality activations
__device__ __half g_mean[BD];         // fp16 mean activation
__device__ __half g_qin [BD];         // fp16 qin
__device__ __half g_x   [BD];         // fp16 LN1 output
__device__ __half g_h   [BF];         // fp16 relu hidden
__device__ __half g_w   [4 * WSZ + 2 * (size_t)DIM * FFN];  // fp16 transposed weights
__device__ float  g_q   [BD];
__device__ float  g_K   [3 * BD];
__device__ float  g_V   [3 * BD];
__device__ float  g_y   [BD];

// ---------------- prep kernels ----------------
// one pass: m0/m1/m2 -> fp16 copies + fp16 mean
__global__ void prep_mods_k(const float4* __restrict__ a, const float4* __restrict__ b,
                            const float4* __restrict__ c,
                            __half2* __restrict__ o0, __half2* __restrict__ o1,
                            __half2* __restrict__ o2, __half2* __restrict__ om, int n4) {
    int i = blockIdx.x * blockDim.x + threadIdx.x;
    int st = gridDim.x * blockDim.x;
    const float third = 1.f / 3.f;
    for (; i < n4; i += st) {
        float4 x = a[i], y = b[i], z = c[i];
        o0[2*i]   = __floats2half2_rn(x.x, x.y);
        o0[2*i+1] = __floats2half2_rn(x.z, x.w);
        o1[2*i]   = __floats2half2_rn(y.x, y.y);
        o1[2*i+1] = __floats2half2_rn(y.z, y.w);
        o2[2*i]   = __floats2half2_rn(z.x, z.y);
        o2[2*i+1] = __floats2half2_rn(z.z, z.w);
        om[2*i]   = __floats2half2_rn((x.x + y.x + z.x) * third, (x.y + y.y + z.y) * third);
        om[2*i+1] = __floats2half2_rn((x.z + y.z + z.z) * third, (x.w + y.w + z.w) * third);
    }
}
// Wt[n][k] = (half)W[k][n]
__global__ void transpose_half_k(const float* __restrict__ W, __half* __restrict__ Wt,
                                 int K, int N) {
    __shared__ float t[32][33];
    int nb = blockIdx.x * 32, kb = blockIdx.y * 32;
    int tx = threadIdx.x, ty = threadIdx.y;
    #pragma unroll
    for (int r = 0; r < 32; r += 8)
        t[ty + r][tx] = W[(size_t)(kb + ty + r) * N + nb + tx];
    __syncthreads();
    #pragma unroll
    for (int r = 0; r < 32; r += 8)
        Wt[(size_t)(nb + ty + r) * K + kb + tx] = __float2half(t[tx][ty + r]);
}

// ---------------- fp16 mma.sync GEMM ----------------
// C[M,N] = A[M,K] @ Wt[N,K]^T + bias. Tiles 128x128x32, 256 thr, 8 warps (4m x 2n),
// warp tile 32x64 = 2 x 8 mma(m16n8k16). cp.async double-buffered fp16 smem.
#define BM 128
#define BN 128
#define BK 32
#define ASTR 40                      // halves per A row (32 + 8 pad)
#define BSTR 40                      // halves per B (n-major) row
#define A_ELEMS (BM * ASTR)          // 5120 halves
#define B_ELEMS (BN * BSTR)          // 5120 halves
#define GSMEM ((2 * (A_ELEMS + B_ELEMS)) * 2)   // 40960 bytes

// MODE: 0 = +bias -> float out; 1 = +bias+addsrc -> half out; 2 = relu(+bias) -> half out
template <int MODE, typename OutT>
__global__ __launch_bounds__(256, 2) void gemm_fp16(
    const __half* __restrict__ A0, const __half* __restrict__ A1, const __half* __restrict__ A2,
    const __half* __restrict__ Wt, const float* __restrict__ bias,
    const float* __restrict__ addsrc,
    OutT* __restrict__ C0, OutT* __restrict__ C1, OutT* __restrict__ C2,
    int K, int Nc)
{
    extern __shared__ __align__(16) __half smh[];
    __half* As = smh;
    __half* Bs = smh + 2 * A_ELEMS;

    const __half* A = (blockIdx.z == 0) ? A0 : (blockIdx.z == 1) ? A1 : A2;
    OutT*         C = (blockIdx.z == 0) ? C0 : (blockIdx.z == 1) ? C1 : C2;

    const int m0 = blockIdx.y * BM, n0 = blockIdx.x * BN;
    const int tid  = threadIdx.x;
    const int lane = tid & 31, warp = tid >> 5;
    const int wm = warp & 3, wn = warp >> 2;
    const int g = lane >> 2, tig = lane & 3;

    const uint32_t sm_a = (uint32_t)__cvta_generic_to_shared(As);
    const uint32_t sm_b = (uint32_t)__cvta_generic_to_shared(Bs);

    auto load_stage = [&](int stage, int kb) {
        const __half* Ag = A + (size_t)m0 * K + kb;
        #pragma unroll
        for (int p = 0; p < 2; p++) {
            int cidx = tid + p * 256;
            int m = cidx >> 2, sg = cidx & 3;          // 4 x 16B segments per 32-half row
            uint32_t dst = sm_a + (uint32_t)(stage * A_ELEMS + m * ASTR + sg * 8) * 2;
            const __half* src = Ag + (size_t)m * K + sg * 8;
            asm volatile("cp.async.cg.shared.global [%0], [%1], 16;\n" :: "r"(dst), "l"(src));
        }
        const __half* Bg = Wt + (size_t)n0 * K + kb;
        #pragma unroll
        for (int p = 0; p < 2; p++) {
            int cidx = tid + p * 256;
            int n = cidx >> 2, sg = cidx & 3;
            uint32_t dst = sm_b + (uint32_t)(stage * B_ELEMS + n * BSTR + sg * 8) * 2;
            const __half* src = Bg + (size_t)n * K + sg * 8;
            asm volatile("cp.async.cg.shared.global [%0], [%1], 16;\n" :: "r"(dst), "l"(src));
        }
    };

    float c[2][8][4];
    #pragma unroll
    for (int i = 0; i < 2; i++)
        #pragma unroll
        for (int j = 0; j < 8; j++)
            #pragma unroll
            for (int l = 0; l < 4; l++) c[i][j][l] = 0.f;

    load_stage(0, 0);
    asm volatile("cp.async.commit_group;\n");
    asm volatile("cp.async.wait_group 0;\n");
    __syncthreads();

    const int KT = K / BK;
    for (int kt = 0; kt < KT; ++kt) {
        int cur = kt & 1;
        if (kt + 1 < KT) {
            load_stage(cur ^ 1, (kt + 1) * BK);
            asm volatile("cp.async.commit_group;\n");
        }
        const __half* as = As + cur * A_ELEMS;
        const __half* bs = Bs + cur * B_ELEMS;
        #pragma unroll
        for (int kk = 0; kk < BK; kk += 16) {
            uint32_t a[2][4], b[8][2];
            #pragma unroll
            for (int mi = 0; mi < 2; mi++) {
                int r = wm * 32 + mi * 16 + g;
                const __half* ap = as + r * ASTR + kk + 2 * tig;
                a[mi][0] = *(const uint32_t*)(ap);
                a[mi][1] = *(const uint32_t*)(ap + 8 * ASTR);
                a[mi][2] = *(const uint32_t*)(ap + 8);
                a[mi][3] = *(const uint32_t*)(ap + 8 * ASTR + 8);
            }
            #pragma unroll
            for (int ni = 0; ni < 8; ni++) {
                int col = wn * 64 + ni * 8 + g;
                const __half* bp = bs + col * BSTR + kk + 2 * tig;
                b[ni][0] = *(const uint32_t*)(bp);
                b[ni][1] = *(const uint32_t*)(bp + 8);
            }
            #pragma unroll
            for (int mi = 0; mi < 2; mi++)
                #pragma unroll
                for (int ni = 0; ni < 8; ni++) {
                    float* cc = c[mi][ni];
                    asm volatile(
                        "mma.sync.aligned.m16n8k16.row.col.f32.f16.f16.f32 "
                        "{%0,%1,%2,%3},{%4,%5,%6,%7},{%8,%9},{%0,%1,%2,%3};\n"
                        : "+f"(cc[0]), "+f"(cc[1]), "+f"(cc[2]), "+f"(cc[3])
                        : "r"(a[mi][0]), "r"(a[mi][1]), "r"(a[mi][2]), "r"(a[mi][3]),
                          "r"(b[ni][0]), "r"(b[ni][1]));
                }
        }
        if (kt + 1 < KT) {
            asm volatile("cp.async.wait_group 0;\n");
            __syncthreads();
        }
    }

    // epilogue
    #pragma unroll
    for (int mi = 0; mi < 2; mi++) {
        int row = m0 + wm * 32 + mi * 16 + g;
        #pragma unroll
        for (int ni = 0; ni < 8; ni++) {
            int col = n0 + wn * 64 + ni * 8 + tig * 2;
            float bv0 = bias[col], bv1 = bias[col + 1];
            float v0 = c[mi][ni][0] + bv0, v1 = c[mi][ni][1] + bv1;
            float v2 = c[mi][ni][2] + bv0, v3 = c[mi][ni][3] + bv1;
            size_t i0 = (size_t)row * Nc + col;
            size_t i1 = (size_t)(row + 8) * Nc + col;
            if (MODE == 1) {
                v0 += addsrc[i0]; v1 += addsrc[i0 + 1];
                v2 += addsrc[i1]; v3 += addsrc[i1 + 1];
            } else if (MODE == 2) {
                v0 = fmaxf(v0, 0.f); v1 = fmaxf(v1, 0.f);
                v2 = fmaxf(v2, 0.f); v3 = fmaxf(v3, 0.f);
            }
            if (MODE == 0) {
                *(float2*)&((float*)C)[i0] = make_float2(v0, v1);
                *(float2*)&((float*)C)[i1] = make_float2(v2, v3);
            } else {
                *(__half2*)&((__half*)C)[i0] = __floats2half2_rn(v0, v1);
                *(__half2*)&((__half*)C)[i1] = __floats2half2_rn(v2, v3);
            }
        }
    }
}

// ---------------- attention (3 keys) + residual + LN1 ----------------
__global__ __launch_bounds__(512) void attn_ln1_k(
    const float* __restrict__ q,
    const float* __restrict__ K0, const float* __restrict__ K1, const float* __restrict__ K2,
    const float* __restrict__ V0, const float* __restrict__ V1, const float* __restrict__ V2,
    const float* __restrict__ dom, const float* __restrict__ gam, const float* __restrict__ bet,
    __half* __restrict__ xo)
{
    __shared__ float sout[DIM];
    __shared__ float rS[16], rQ[16], stats[2];
    const int b = blockIdx.x, tid = threadIdx.x;
    const int h = tid >> 5, lane = tid & 31;
    const size_t rowb = (size_t)b * DIM;
    const size_t off = rowb + h * HD + lane * 2;

    float2 qv = *(const float2*)(q + off);
    float2 k0 = *(const float2*)(K0 + off);
    float2 k1 = *(const float2*)(K1 + off);
    float2 k2 = *(const float2*)(K2 + off);
    float d0 = qv.x * k0.x + qv.y * k0.y;
    float d1 = qv.x * k1.x + qv.y * k1.y;
    float d2 = qv.x * k2.x + qv.y * k2.y;
    #pragma unroll
    for (int o = 16; o; o >>= 1) {
        d0 += __shfl_xor_sync(0xffffffffu, d0, o);
        d1 += __shfl_xor_sync(0xffffffffu, d1, o);
        d2 += __shfl_xor_sync(0xffffffffu, d2, o);
    }
    float s0 = d0 * 0.125f, s1 = d1 * 0.125f, s2 = d2 * 0.125f;
    float mx = fmaxf(s0, fmaxf(s1, s2));
    float e0 = expf(s0 - mx), e1 = expf(s1 - mx), e2 = expf(s2 - mx);
    float inv = 1.f / (e0 + e1 + e2);
    float p0 = e0 * inv, p1 = e1 * inv, p2 = e2 * inv;

    float2 v0 = *(const float2*)(V0 + off);
    float2 v1 = *(const float2*)(V1 + off);
    float2 v2 = *(const float2*)(V2 + off);
    float ox = p0 * v0.x + p1 * v1.x + p2 * v2.x;
    float oy = p0 * v0.y + p1 * v1.y + p2 * v2.y;
    int dloc = h * HD + lane * 2;
    sout[dloc] = ox;
    sout[dloc + 1] = oy;
    __syncthreads();

    int d0i = tid * 2;
    float t0 = dom[rowb + d0i]     + sout[d0i];
    float t1 = dom[rowb + d0i + 1] + sout[d0i + 1];
    float s = t0 + t1, sq = t0 * t0 + t1 * t1;
    #pragma unroll
    for (int o = 16; o; o >>= 1) {
        s  += __shfl_xor_sync(0xffffffffu, s, o);
        sq += __shfl_xor_sync(0xffffffffu, sq, o);
    }
    if (lane == 0) { rS[h] = s; rQ[h] = sq; }
    __syncthreads();
    if (tid == 0) {
        float S = 0.f, Q = 0.f;
        #pragma unroll
        for (int i = 0; i < 16; i++) { S += rS[i]; Q += rQ[i]; }
        float mu = S * (1.f / DIM);
        float var = Q * (1.f / DIM) - mu * mu;
        stats[0] = mu;
        stats[1] = rsqrtf(var + LNEPS);
    }
    __syncthreads();
    float mu = stats[0], r = stats[1];
    float x0 = (t0 - mu) * r * gam[d0i]     + bet[d0i];
    float x1 = (t1 - mu) * r * gam[d0i + 1] + bet[d0i + 1];
    *(__half2*)(xo + rowb + d0i) = __floats2half2_rn(x0, x1);
}

// ---------------- residual + LN2 + [DIM,3] matvec + softmax ----------------
__global__ __launch_bounds__(256) void final_k(
    const __half* __restrict__ x, const float* __restrict__ y,
    const float* __restrict__ g2, const float* __restrict__ b2,
    const float* __restrict__ Ww, const float* __restrict__ bw,
    float* __restrict__ out)
{
    __shared__ float rs[8], rq[8], rl[8][3], stats[2];
    const int b = blockIdx.x, tid = threadIdx.x;
    const int lane = tid & 31, w = tid >> 5;
    const size_t base = (size_t)b * DIM;

    float t[4];
    float s = 0.f, sq = 0.f;
    #pragma unroll
    for (int i = 0; i < 4; i++) {
        int d = tid + i * 256;
        float v = __half2float(x[base + d]) + y[base + d];
        t[i] = v; s += v; sq += v * v;
    }
    #pragma unroll
    for (int o = 16; o; o >>= 1) {
        s  += __shfl_xor_sync(0xffffffffu, s, o);
        sq += __shfl_xor_sync(0xffffffffu, sq, o);
    }
    if (lane == 0) { rs[w] = s; rq[w] = sq; }
    __syncthreads();
    if (tid == 0) {
        float S = 0.f, Q = 0.f;
        #pragma unroll
        for (int i = 0; i < 8; i++) { S += rs[i]; Q += rq[i]; }
        float mu = S * (1.f / DIM);
        float var = Q * (1.f / DIM) - mu * mu;
        stats[0] = mu;
        stats[1] = rsqrtf(var + LNEPS);
    }
    __syncthreads();
    float mu = stats[0], r = stats[1];
    float l0 = 0.f, l1 = 0.f, l2 = 0.f;
    #pragma unroll
    for (int i = 0; i < 4; i++) {
        int d = tid + i * 256;
        float xn = (t[i] - mu) * r * g2[d] + b2[d];
        l0 += xn * Ww[d * 3];
        l1 += xn * Ww[d * 3 + 1];
        l2 += xn * Ww[d * 3 + 2];
    }
    #pragma unroll
    for (int o = 16; o; o >>= 1) {
        l0 += __shfl_xor_sync(0xffffffffu, l0, o);
        l1 += __shfl_xor_sync(0xffffffffu, l1, o);
        l2 += __shfl_xor_sync(0xffffffffu, l2, o);
    }
    if (lane == 0) { rl[w][0] = l0; rl[w][1] = l1; rl[w][2] = l2; }
    __syncthreads();
    if (tid == 0) {
        float a0 = bw[0], a1 = bw[1], a2 = bw[2];
        #pragma unroll
        for (int i = 0; i < 8; i++) { a0 += rl[i][0]; a1 += rl[i][1]; a2 += rl[i][2]; }
        float m = fmaxf(a0, fmaxf(a1, a2));
        float e0 = expf(a0 - m), e1 = expf(a1 - m), e2 = expf(a2 - m);
        float inv = 1.f / (e0 + e1 + e2);
        out[(size_t)b * 3]     = e0 * inv;
        out[(size_t)b * 3 + 1] = e1 * inv;
        out[(size_t)b * 3 + 2] = e2 * inv;
    }
}

// ---------------- host launcher ----------------
extern "C" void kernel_launch(void* const* d_in, const int* in_sizes, int n_in,
                              void* d_out, int out_size)
{
    (void)in_sizes; (void)n_in; (void)out_size;
    const float* m0  = (const float*)d_in[0];
    const float* m1  = (const float*)d_in[1];
    const float* m2  = (const float*)d_in[2];
    const float* dom = (const float*)d_in[3];
    const float* Wg  = (const float*)d_in[4];
    const float* bg  = (const float*)d_in[5];
    const float* Wq  = (const float*)d_in[6];
    const float* bq  = (const float*)d_in[7];
    const float* Wk  = (const float*)d_in[8];
    const float* bk  = (const float*)d_in[9];
    const float* Wv  = (const float*)d_in[10];
    const float* bv  = (const float*)d_in[11];
    const float* W1  = (const float*)d_in[12];
    const float* b1  = (const float*)d_in[13];
    const float* W2  = (const float*)d_in[14];
    const float* b2  = (const float*)d_in[15];
    const float* g1  = (const float*)d_in[16];
    const float* be1 = (const float*)d_in[17];
    const float* g2  = (const float*)d_in[18];
    const float* be2 = (const float*)d_in[19];
    const float* Ww  = (const float*)d_in[20];
    const float* bw  = (const float*)d_in[21];
    float* out = (float*)d_out;

    __half *pmods, *pmean, *pqin, *px, *ph, *pw;
    float  *pq, *pK, *pV, *py;
    cudaGetSymbolAddress((void**)&pmods, g_mods);
    cudaGetSymbolAddress((void**)&pmean, g_mean);
    cudaGetSymbolAddress((void**)&pqin,  g_qin);
    cudaGetSymbolAddress((void**)&px,    g_x);
    cudaGetSymbolAddress((void**)&ph,    g_h);
    cudaGetSymbolAddress((void**)&pw,    g_w);
    cudaGetSymbolAddress((void**)&pq,    g_q);
    cudaGetSymbolAddress((void**)&pK,    g_K);
    cudaGetSymbolAddress((void**)&pV,    g_V);
    cudaGetSymbolAddress((void**)&py,    g_y);

    __half* Wgt = pw;                              // [1024,1024]
    __half* Wqt = pw + (size_t)WSZ;
    __half* Wkt = pw + (size_t)2 * WSZ;
    __half* Wvt = pw + (size_t)3 * WSZ;
    __half* W1t = pw + (size_t)4 * WSZ;            // [4096,1024]
    __half* W2t = W1t + (size_t)DIM * FFN;         // [1024,4096]

    dim3 tb(32, 8);
    transpose_half_k<<<dim3(32, 32),  tb>>>(Wg, Wgt, DIM, DIM);
    transpose_half_k<<<dim3(32, 32),  tb>>>(Wq, Wqt, DIM, DIM);
    transpose_half_k<<<dim3(32, 32),  tb>>>(Wk, Wkt, DIM, DIM);
    transpose_half_k<<<dim3(32, 32),  tb>>>(Wv, Wvt, DIM, DIM);
    transpose_half_k<<<dim3(128, 32), tb>>>(W1, W1t, DIM, FFN);   // -> [4096][1024]
    transpose_half_k<<<dim3(32, 128), tb>>>(W2, W2t, FFN, DIM);   // -> [1024][4096]

    prep_mods_k<<<8192, 256>>>((const float4*)m0, (const float4*)m1, (const float4*)m2,
                               (__half2*)pmods, (__half2*)(pmods + BD),
                               (__half2*)(pmods + 2 * BD), (__half2*)pmean, (int)(BD / 4));

    dim3 gD(DIM / BN, BB / BM, 1);
    dim3 gF(FFN / BN, BB / BM, 1);
    dim3 gKV(DIM / BN, BB / BM, 3);

    // qin = half( domain + mean@Wg + bg )
    gemm_fp16<1, __half><<<gD, 256, GSMEM>>>(pmean, pmean, pmean, Wgt, bg, dom,
                                             pqin, pqin, pqin, DIM, DIM);
    // q = qin@Wq + bq  (fp32 out)
    gemm_fp16<0, float><<<gD, 256, GSMEM>>>(pqin, pqin, pqin, Wqt, bq, nullptr,
                                            pq, pq, pq, DIM, DIM);
    // K_j = m_j@Wk + bk
    gemm_fp16<0, float><<<gKV, 256, GSMEM>>>(pmods, pmods + BD, pmods + 2 * BD, Wkt, bk, nullptr,
                                             pK, pK + BD, pK + 2 * BD, DIM, DIM);
    // V_j = m_j@Wv + bv
    gemm_fp16<0, float><<<gKV, 256, GSMEM>>>(pmods, pmods + BD, pmods + 2 * BD, Wvt, bv, nullptr,
                                             pV, pV + BD, pV + 2 * BD, DIM, DIM);

    attn_ln1_k<<<BB, 512>>>(pq, pK, pK + BD, pK + 2 * BD,
                            pV, pV + BD, pV + 2 * BD,
                            dom, g1, be1, px);

    // h = half(relu(x@W1 + b1))
    gemm_fp16<2, __half><<<gF, 256, GSMEM>>>(px, px, px, W1t, b1, nullptr,
                                             ph, ph, ph, DIM, FFN);
    // y = h@W2 + b2  (fp32 out)
    gemm_fp16<0, float><<<gD, 256, GSMEM>>>(ph, ph, ph, W2t, b2, nullptr,
                                            py, py, py, FFN, DIM);

    final_k<<<BB, 256>>>(px, py, g2, be2, Ww, bw, out);
}

// round 7
// speedup vs baseline: 2.0816x; 1.1590x over previous
#include <cuda_runtime.h>
#include <cuda_fp16.h>
#include <math.h>
#include <stdint.h>

// ---------------- problem constants ----------------
#define BB   16384
#define DIM  1024
#define HH   16
#define HD   64
#define FFN  4096
#define LNEPS 1e-5f

#define BD   ((size_t)BB * DIM)
#define BF   ((size_t)BB * FFN)
#define WSZ  (1024*1024)

// ---------------- scratch ----------------
__device__ __half g_mods[3 * BD];     // fp16 modality activations
__device__ __half g_mean[BD];         // fp16 mean activation
__device__ __half g_qin [BD];         // fp16 qin
__device__ __half g_x   [BD];         // fp16 LN1 output
__device__ __half g_h   [BF];         // fp16 relu hidden
__device__ __half g_q   [BD];         // fp16 q
__device__ __half g_K   [3 * BD];     // fp16 K
__device__ __half g_V   [3 * BD];     // fp16 V
__device__ __half g_w   [4 * WSZ + 2 * (size_t)DIM * FFN];  // fp16 transposed weights
__device__ float  g_y   [BD];

// ---------------- prep kernels ----------------
__global__ void prep_mods_k(const float4* __restrict__ a, const float4* __restrict__ b,
                            const float4* __restrict__ c,
                            __half2* __restrict__ o0, __half2* __restrict__ o1,
                            __half2* __restrict__ o2, __half2* __restrict__ om, int n4) {
    int i = blockIdx.x * blockDim.x + threadIdx.x;
    int st = gridDim.x * blockDim.x;
    const float third = 1.f / 3.f;
    for (; i < n4; i += st) {
        float4 x = a[i], y = b[i], z = c[i];
        o0[2*i]   = __floats2half2_rn(x.x, x.y);
        o0[2*i+1] = __floats2half2_rn(x.z, x.w);
        o1[2*i]   = __floats2half2_rn(y.x, y.y);
        o1[2*i+1] = __floats2half2_rn(y.z, y.w);
        o2[2*i]   = __floats2half2_rn(z.x, z.y);
        o2[2*i+1] = __floats2half2_rn(z.z, z.w);
        om[2*i]   = __floats2half2_rn((x.x + y.x + z.x) * third, (x.y + y.y + z.y) * third);
        om[2*i+1] = __floats2half2_rn((x.z + y.z + z.z) * third, (x.w + y.w + z.w) * third);
    }
}
// Wt[n][k] = (half)W[k][n]
__global__ void transpose_half_k(const float* __restrict__ W, __half* __restrict__ Wt,
                                 int K, int N) {
    __shared__ float t[32][33];
    int nb = blockIdx.x * 32, kb = blockIdx.y * 32;
    int tx = threadIdx.x, ty = threadIdx.y;
    #pragma unroll
    for (int r = 0; r < 32; r += 8)
        t[ty + r][tx] = W[(size_t)(kb + ty + r) * N + nb + tx];
    __syncthreads();
    #pragma unroll
    for (int r = 0; r < 32; r += 8)
        Wt[(size_t)(nb + ty + r) * K + kb + tx] = __float2half(t[tx][ty + r]);
}

// ---------------- fp16 mma.sync GEMM (ldmatrix + 3-stage cp.async) -------------
// C[M,N] = A[M,K] @ Wt[N,K]^T + bias. Tiles 128x128x32, 256 thr, 8 warps (4m x 2n),
// warp tile 32x64 = 2 x 8 mma(m16n8k16).
#define BM 128
#define BN 128
#define BK 32
#define NSTG 3
#define ASTR 40                      // halves per A row (32 + 8 pad -> conflict-free LDSM phases)
#define BSTR 40
#define A_ELEMS (BM * ASTR)          // 5120 halves / stage
#define B_ELEMS (BN * BSTR)
#define GSMEM (NSTG * (A_ELEMS + B_ELEMS) * 2)   // 61440 bytes

__device__ __forceinline__ void ldsm4(uint32_t* r, uint32_t addr) {
    asm volatile("ldmatrix.sync.aligned.m8n8.x4.shared.b16 {%0,%1,%2,%3}, [%4];"
                 : "=r"(r[0]), "=r"(r[1]), "=r"(r[2]), "=r"(r[3]) : "r"(addr));
}

// MODE: 0 = +bias; 1 = +bias+addsrc; 2 = relu(+bias). OutT = __half or float.
template <int MODE, typename OutT>
__global__ __launch_bounds__(256, 2) void gemm_fp16(
    const __half* __restrict__ A0, const __half* __restrict__ A1, const __half* __restrict__ A2,
    const __half* __restrict__ Wt, const float* __restrict__ bias,
    const float* __restrict__ addsrc,
    OutT* __restrict__ C0, OutT* __restrict__ C1, OutT* __restrict__ C2,
    int K, int Nc)
{
    extern __shared__ __align__(16) __half smh[];
    __half* As = smh;
    __half* Bs = smh + NSTG * A_ELEMS;

    const __half* A = (blockIdx.z == 0) ? A0 : (blockIdx.z == 1) ? A1 : A2;
    OutT*         C = (blockIdx.z == 0) ? C0 : (blockIdx.z == 1) ? C1 : C2;

    const int m0 = blockIdx.y * BM, n0 = blockIdx.x * BN;
    const int tid  = threadIdx.x;
    const int lane = tid & 31, warp = tid >> 5;
    const int wm = warp & 3, wn = warp >> 2;
    const int g = lane >> 2, tig = lane & 3;

    const uint32_t sm_a = (uint32_t)__cvta_generic_to_shared(As);
    const uint32_t sm_b = (uint32_t)__cvta_generic_to_shared(Bs);

    // ldmatrix per-thread offsets (in halves, within a stage)
    const int a_off = (wm * 32 + (lane & 15)) * ASTR + (lane >> 4) * 8;
    const int b_off = (wn * 64 + (lane & 7) + ((lane >= 16) ? 8 : 0)) * BSTR
                    + ((lane >> 3) & 1) * 8;

    auto load_stage = [&](int stage, int kb) {
        const __half* Ag = A + (size_t)m0 * K + kb;
        #pragma unroll
        for (int p = 0; p < 2; p++) {
            int cidx = tid + p * 256;
            int m = cidx >> 2, sg = cidx & 3;
            uint32_t dst = sm_a + (uint32_t)(stage * A_ELEMS + m * ASTR + sg * 8) * 2;
            const __half* src = Ag + (size_t)m * K + sg * 8;
            asm volatile("cp.async.cg.shared.global [%0], [%1], 16;\n" :: "r"(dst), "l"(src));
        }
        const __half* Bg = Wt + (size_t)n0 * K + kb;
        #pragma unroll
        for (int p = 0; p < 2; p++) {
            int cidx = tid + p * 256;
            int n = cidx >> 2, sg = cidx & 3;
            uint32_t dst = sm_b + (uint32_t)(stage * B_ELEMS + n * BSTR + sg * 8) * 2;
            const __half* src = Bg + (size_t)n * K + sg * 8;
            asm volatile("cp.async.cg.shared.global [%0], [%1], 16;\n" :: "r"(dst), "l"(src));
        }
        asm volatile("cp.async.commit_group;\n");
    };

    float c[2][8][4];
    #pragma unroll
    for (int i = 0; i < 2; i++)
        #pragma unroll
        for (int j = 0; j < 8; j++)
            #pragma unroll
            for (int l = 0; l < 4; l++) c[i][j][l] = 0.f;

    load_stage(0, 0);
    load_stage(1, BK);

    const int KT = K / BK;
    for (int kt = 0; kt < KT; ++kt) {
        if (kt + 1 < KT) asm volatile("cp.async.wait_group 1;\n");
        else             asm volatile("cp.async.wait_group 0;\n");
        __syncthreads();   // stage kt ready AND all warps done with stage (kt-1)%3

        if (kt + 2 < KT) load_stage((kt + 2) % NSTG, (kt + 2) * BK);

        const int cur = kt % NSTG;
        const uint32_t abase = sm_a + (uint32_t)(cur * A_ELEMS + a_off) * 2;
        const uint32_t bbase = sm_b + (uint32_t)(cur * B_ELEMS + b_off) * 2;

        #pragma unroll
        for (int kk = 0; kk < BK; kk += 16) {
            uint32_t a[2][4], b[8][2];
            #pragma unroll
            for (int mi = 0; mi < 2; mi++)
                ldsm4(a[mi], abase + (uint32_t)(mi * 16 * ASTR + kk) * 2);
            #pragma unroll
            for (int nip = 0; nip < 4; nip++) {
                uint32_t r[4];
                ldsm4(r, bbase + (uint32_t)(nip * 16 * BSTR + kk) * 2);
                b[2 * nip][0]     = r[0];
                b[2 * nip][1]     = r[1];
                b[2 * nip + 1][0] = r[2];
                b[2 * nip + 1][1] = r[3];
            }
            #pragma unroll
            for (int mi = 0; mi < 2; mi++)
                #pragma unroll
                for (int ni = 0; ni < 8; ni++) {
                    float* cc = c[mi][ni];
                    asm volatile(
                        "mma.sync.aligned.m16n8k16.row.col.f32.f16.f16.f32 "
                        "{%0,%1,%2,%3},{%4,%5,%6,%7},{%8,%9},{%0,%1,%2,%3};\n"
                        : "+f"(cc[0]), "+f"(cc[1]), "+f"(cc[2]), "+f"(cc[3])
                        : "r"(a[mi][0]), "r"(a[mi][1]), "r"(a[mi][2]), "r"(a[mi][3]),
                          "r"(b[ni][0]), "r"(b[ni][1]));
                }
        }
    }

    // epilogue
    #pragma unroll
    for (int mi = 0; mi < 2; mi++) {
        int row = m0 + wm * 32 + mi * 16 + g;
        #pragma unroll
        for (int ni = 0; ni < 8; ni++) {
            int col = n0 + wn * 64 + ni * 8 + tig * 2;
            float bv0 = bias[col], bv1 = bias[col + 1];
            float v0 = c[mi][ni][0] + bv0, v1 = c[mi][ni][1] + bv1;
            float v2 = c[mi][ni][2] + bv0, v3 = c[mi][ni][3] + bv1;
            size_t i0 = (size_t)row * Nc + col;
            size_t i1 = (size_t)(row + 8) * Nc + col;
            if (MODE == 1) {
                v0 += addsrc[i0]; v1 += addsrc[i0 + 1];
                v2 += addsrc[i1]; v3 += addsrc[i1 + 1];
            } else if (MODE == 2) {
                v0 = fmaxf(v0, 0.f); v1 = fmaxf(v1, 0.f);
                v2 = fmaxf(v2, 0.f); v3 = fmaxf(v3, 0.f);
            }
            if (sizeof(OutT) == 2) {
                *(__half2*)&((__half*)C)[i0] = __floats2half2_rn(v0, v1);
                *(__half2*)&((__half*)C)[i1] = __floats2half2_rn(v2, v3);
            } else {
                *(float2*)&((float*)C)[i0] = make_float2(v0, v1);
                *(float2*)&((float*)C)[i1] = make_float2(v2, v3);
            }
        }
    }
}

// ---------------- attention (3 keys) + residual + LN1, fp16 q/K/V ----------------
__global__ __launch_bounds__(512) void attn_ln1_k(
    const __half* __restrict__ q,
    const __half* __restrict__ K0, const __half* __restrict__ K1, const __half* __restrict__ K2,
    const __half* __restrict__ V0, const __half* __restrict__ V1, const __half* __restrict__ V2,
    const float* __restrict__ dom, const float* __restrict__ gam, const float* __restrict__ bet,
    __half* __restrict__ xo)
{
    __shared__ float sout[DIM];
    __shared__ float rS[16], rQ[16], stats[2];
    const int b = blockIdx.x, tid = threadIdx.x;
    const int h = tid >> 5, lane = tid & 31;
    const size_t rowb = (size_t)b * DIM;
    const size_t off = rowb + h * HD + lane * 2;

    float2 qv = __half22float2(*(const __half2*)(q + off));
    float2 k0 = __half22float2(*(const __half2*)(K0 + off));
    float2 k1 = __half22float2(*(const __half2*)(K1 + off));
    float2 k2 = __half22float2(*(const __half2*)(K2 + off));
    float d0 = qv.x * k0.x + qv.y * k0.y;
    float d1 = qv.x * k1.x + qv.y * k1.y;
    float d2 = qv.x * k2.x + qv.y * k2.y;
    #pragma unroll
    for (int o = 16; o; o >>= 1) {
        d0 += __shfl_xor_sync(0xffffffffu, d0, o);
        d1 += __shfl_xor_sync(0xffffffffu, d1, o);
        d2 += __shfl_xor_sync(0xffffffffu, d2, o);
    }
    float s0 = d0 * 0.125f, s1 = d1 * 0.125f, s2 = d2 * 0.125f;
    float mx = fmaxf(s0, fmaxf(s1, s2));
    float e0 = expf(s0 - mx), e1 = expf(s1 - mx), e2 = expf(s2 - mx);
    float inv = 1.f / (e0 + e1 + e2);
    float p0 = e0 * inv, p1 = e1 * inv, p2 = e2 * inv;

    float2 v0 = __half22float2(*(const __half2*)(V0 + off));
    float2 v1 = __half22float2(*(const __half2*)(V1 + off));
    float2 v2 = __half22float2(*(const __half2*)(V2 + off));
    float ox = p0 * v0.x + p1 * v1.x + p2 * v2.x;
    float oy = p0 * v0.y + p1 * v1.y + p2 * v2.y;
    int dloc = h * HD + lane * 2;
    sout[dloc] = ox;
    sout[dloc + 1] = oy;
    __syncthreads();

    int d0i = tid * 2;
    float t0 = dom[rowb + d0i]     + sout[d0i];
    float t1 = dom[rowb + d0i + 1] + sout[d0i + 1];
    float s = t0 + t1, sq = t0 * t0 + t1 * t1;
    #pragma unroll
    for (int o = 16; o; o >>= 1) {
        s  += __shfl_xor_sync(0xffffffffu, s, o);
        sq += __shfl_xor_sync(0xffffffffu, sq, o);
    }
    if (lane == 0) { rS[h] = s; rQ[h] = sq; }
    __syncthreads();
    if (tid == 0) {
        float S = 0.f, Q = 0.f;
        #pragma unroll
        for (int i = 0; i < 16; i++) { S += rS[i]; Q += rQ[i]; }
        float mu = S * (1.f / DIM);
        float var = Q * (1.f / DIM) - mu * mu;
        stats[0] = mu;
        stats[1] = rsqrtf(var + LNEPS);
    }
    __syncthreads();
    float mu = stats[0], r = stats[1];
    float x0 = (t0 - mu) * r * gam[d0i]     + bet[d0i];
    float x1 = (t1 - mu) * r * gam[d0i + 1] + bet[d0i + 1];
    *(__half2*)(xo + rowb + d0i) = __floats2half2_rn(x0, x1);
}

// ---------------- residual + LN2 + [DIM,3] matvec + softmax ----------------
__global__ __launch_bounds__(256) void final_k(
    const __half* __restrict__ x, const float* __restrict__ y,
    const float* __restrict__ g2, const float* __restrict__ b2,
    const float* __restrict__ Ww, const float* __restrict__ bw,
    float* __restrict__ out)
{
    __shared__ float rs[8], rq[8], rl[8][3], stats[2];
    const int b = blockIdx.x, tid = threadIdx.x;
    const int lane = tid & 31, w = tid >> 5;
    const size_t base = (size_t)b * DIM;

    float t[4];
    float s = 0.f, sq = 0.f;
    #pragma unroll
    for (int i = 0; i < 4; i++) {
        int d = tid + i * 256;
        float v = __half2float(x[base + d]) + y[base + d];
        t[i] = v; s += v; sq += v * v;
    }
    #pragma unroll
    for (int o = 16; o; o >>= 1) {
        s  += __shfl_xor_sync(0xffffffffu, s, o);
        sq += __shfl_xor_sync(0xffffffffu, sq, o);
    }
    if (lane == 0) { rs[w] = s; rq[w] = sq; }
    __syncthreads();
    if (tid == 0) {
        float S = 0.f, Q = 0.f;
        #pragma unroll
        for (int i = 0; i < 8; i++) { S += rs[i]; Q += rq[i]; }
        float mu = S * (1.f / DIM);
        float var = Q * (1.f / DIM) - mu * mu;
        stats[0] = mu;
        stats[1] = rsqrtf(var + LNEPS);
    }
    __syncthreads();
    float mu = stats[0], r = stats[1];
    float l0 = 0.f, l1 = 0.f, l2 = 0.f;
    #pragma unroll
    for (int i = 0; i < 4; i++) {
        int d = tid + i * 256;
        float xn = (t[i] - mu) * r * g2[d] + b2[d];
        l0 += xn * Ww[d * 3];
        l1 += xn * Ww[d * 3 + 1];
        l2 += xn * Ww[d * 3 + 2];
    }
    #pragma unroll
    for (int o = 16; o; o >>= 1) {
        l0 += __shfl_xor_sync(0xffffffffu, l0, o);
        l1 += __shfl_xor_sync(0xffffffffu, l1, o);
        l2 += __shfl_xor_sync(0xffffffffu, l2, o);
    }
    if (lane == 0) { rl[w][0] = l0; rl[w][1] = l1; rl[w][2] = l2; }
    __syncthreads();
    if (tid == 0) {
        float a0 = bw[0], a1 = bw[1], a2 = bw[2];
        #pragma unroll
        for (int i = 0; i < 8; i++) { a0 += rl[i][0]; a1 += rl[i][1]; a2 += rl[i][2]; }
        float m = fmaxf(a0, fmaxf(a1, a2));
        float e0 = expf(a0 - m), e1 = expf(a1 - m), e2 = expf(a2 - m);
        float inv = 1.f / (e0 + e1 + e2);
        out[(size_t)b * 3]     = e0 * inv;
        out[(size_t)b * 3 + 1] = e1 * inv;
        out[(size_t)b * 3 + 2] = e2 * inv;
    }
}

// ---------------- host launcher ----------------
extern "C" void kernel_launch(void* const* d_in, const int* in_sizes, int n_in,
                              void* d_out, int out_size)
{
    (void)in_sizes; (void)n_in; (void)out_size;
    const float* m0  = (const float*)d_in[0];
    const float* m1  = (const float*)d_in[1];
    const float* m2  = (const float*)d_in[2];
    const float* dom = (const float*)d_in[3];
    const float* Wg  = (const float*)d_in[4];
    const float* bg  = (const float*)d_in[5];
    const float* Wq  = (const float*)d_in[6];
    const float* bq  = (const float*)d_in[7];
    const float* Wk  = (const float*)d_in[8];
    const float* bk  = (const float*)d_in[9];
    const float* Wv  = (const float*)d_in[10];
    const float* bv  = (const float*)d_in[11];
    const float* W1  = (const float*)d_in[12];
    const float* b1  = (const float*)d_in[13];
    const float* W2  = (const float*)d_in[14];
    const float* b2  = (const float*)d_in[15];
    const float* g1  = (const float*)d_in[16];
    const float* be1 = (const float*)d_in[17];
    const float* g2  = (const float*)d_in[18];
    const float* be2 = (const float*)d_in[19];
    const float* Ww  = (const float*)d_in[20];
    const float* bw  = (const float*)d_in[21];
    float* out = (float*)d_out;

    __half *pmods, *pmean, *pqin, *px, *ph, *pw, *pq, *pK, *pV;
    float  *py;
    cudaGetSymbolAddress((void**)&pmods, g_mods);
    cudaGetSymbolAddress((void**)&pmean, g_mean);
    cudaGetSymbolAddress((void**)&pqin,  g_qin);
    cudaGetSymbolAddress((void**)&px,    g_x);
    cudaGetSymbolAddress((void**)&ph,    g_h);
    cudaGetSymbolAddress((void**)&pw,    g_w);
    cudaGetSymbolAddress((void**)&pq,    g_q);
    cudaGetSymbolAddress((void**)&pK,    g_K);
    cudaGetSymbolAddress((void**)&pV,    g_V);
    cudaGetSymbolAddress((void**)&py,    g_y);

    __half* Wgt = pw;                              // [1024,1024]
    __half* Wqt = pw + (size_t)WSZ;
    __half* Wkt = pw + (size_t)2 * WSZ;
    __half* Wvt = pw + (size_t)3 * WSZ;
    __half* W1t = pw + (size_t)4 * WSZ;            // [4096,1024]
    __half* W2t = W1t + (size_t)DIM * FFN;         // [1024,4096]

    cudaFuncSetAttribute(gemm_fp16<0, __half>, cudaFuncAttributeMaxDynamicSharedMemorySize, GSMEM);
    cudaFuncSetAttribute(gemm_fp16<1, __half>, cudaFuncAttributeMaxDynamicSharedMemorySize, GSMEM);
    cudaFuncSetAttribute(gemm_fp16<2, __half>, cudaFuncAttributeMaxDynamicSharedMemorySize, GSMEM);
    cudaFuncSetAttribute(gemm_fp16<0, float>,  cudaFuncAttributeMaxDynamicSharedMemorySize, GSMEM);

    dim3 tb(32, 8);
    transpose_half_k<<<dim3(32, 32),  tb>>>(Wg, Wgt, DIM, DIM);
    transpose_half_k<<<dim3(32, 32),  tb>>>(Wq, Wqt, DIM, DIM);
    transpose_half_k<<<dim3(32, 32),  tb>>>(Wk, Wkt, DIM, DIM);
    transpose_half_k<<<dim3(32, 32),  tb>>>(Wv, Wvt, DIM, DIM);
    transpose_half_k<<<dim3(128, 32), tb>>>(W1, W1t, DIM, FFN);   // -> [4096][1024]
    transpose_half_k<<<dim3(32, 128), tb>>>(W2, W2t, FFN, DIM);   // -> [1024][4096]

    prep_mods_k<<<8192, 256>>>((const float4*)m0, (const float4*)m1, (const float4*)m2,
                               (__half2*)pmods, (__half2*)(pmods + BD),
                               (__half2*)(pmods + 2 * BD), (__half2*)pmean, (int)(BD / 4));

    dim3 gD(DIM / BN, BB / BM, 1);
    dim3 gF(FFN / BN, BB / BM, 1);
    dim3 gKV(DIM / BN, BB / BM, 3);

    // qin = half( domain + mean@Wg + bg )
    gemm_fp16<1, __half><<<gD, 256, GSMEM>>>(pmean, pmean, pmean, Wgt, bg, dom,
                                             pqin, pqin, pqin, DIM, DIM);
    // q = half(qin@Wq + bq)
    gemm_fp16<0, __half><<<gD, 256, GSMEM>>>(pqin, pqin, pqin, Wqt, bq, nullptr,
                                             pq, pq, pq, DIM, DIM);
    // K_j = half(m_j@Wk + bk)
    gemm_fp16<0, __half><<<gKV, 256, GSMEM>>>(pmods, pmods + BD, pmods + 2 * BD, Wkt, bk, nullptr,
                                              pK, pK + BD, pK + 2 * BD, DIM, DIM);
    // V_j = half(m_j@Wv + bv)
    gemm_fp16<0, __half><<<gKV, 256, GSMEM>>>(pmods, pmods + BD, pmods + 2 * BD, Wvt, bv, nullptr,
                                              pV, pV + BD, pV + 2 * BD, DIM, DIM);

    attn_ln1_k<<<BB, 512>>>(pq, pK, pK + BD, pK + 2 * BD,
                            pV, pV + BD, pV + 2 * BD,
                            dom, g1, be1, px);

    // h = half(relu(x@W1 + b1))
    gemm_fp16<2, __half><<<gF, 256, GSMEM>>>(px, px, px, W1t, b1, nullptr,
                                             ph, ph, ph, DIM, FFN);
    // y = h@W2 + b2  (fp32 out)
    gemm_fp16<0, float><<<gD, 256, GSMEM>>>(ph, ph, ph, W2t, b2, nullptr,
                                            py, py, py, FFN, DIM);

    final_k<<<BB, 256>>>(px, py, g2, be2, Ww, bw, out);
}